// round 8
// baseline (speedup 1.0000x reference)
#include <cuda_runtime.h>
#include <cuda_bf16.h>

// SAN Subtraction: out[n,c,k,l] = x[n,c,oh,ow] - x[n,c, refl(oh+i-3), refl(ow+j-3)]
//   x: [8, 64, 56, 56] fp32, K=7, pad=3 reflect;  out: [8, 64, 49, 3136] fp32.
//
// R7: finest-grain one-wave configuration.
//   Evidence from R2-R6: dur pinned at 55-60us across store mechanisms
//   (STG.128 vs TMA bulk), occupancy, and LDS patterns -> sustained DRAM
//   write ceiling ~5.7 TB/s is binding. Remaining lever: wave/tail shaping.
//   - Quarter-plane CTAs (14 rows), 64 thr, grid=2048, launch_bounds(64,16):
//     16 CTAs/SM resident, 2368 slots >= 2048 -> whole grid in ONE wave,
//     drain tail at quarter-plane granularity, 16 independent store streams
//     per SM for DRAM queue diversity.
//   - Same proven ~60-reg hot loop (reg cap 64, identical to R5's -> no
//     spill), pre-reflected padded tile, conflict-free RS=88 LDS.128,
//     plain STG.128 (512 B contiguous per warp-store).

#define H 56
#define W 56
#define PLANE (H * W)   // 3136
#define KK 49
#define RPC 14          // output rows per CTA (quarter plane)
#define SROWS 20        // RPC + 2*3 halo
#define PCOLS 62        // W + 6
#define RS 88           // smem row stride in floats (conflict-free for LDS.128)

__global__ __launch_bounds__(64, 16)
void san_subtraction_kernel(const float* __restrict__ x,
                            float* __restrict__ out) {
    __shared__ float sp[SROWS * RS];  // 7.04 KB

    const int plane = blockIdx.x >> 2;
    const int quad  = blockIdx.x & 3;
    const int r0    = quad * RPC;

    const float* __restrict__ xin = x + (size_t)plane * PLANE;

    // Stage pre-reflected padded tile: rows r0-3 .. r0+16, cols -3 .. 58.
    // refl(p) = min(|p|, 110-|p|)  (110 = 2*(H-1))
    for (int t = threadIdx.x; t < SROWS * PCOLS; t += 64) {
        const int lr = t / PCOLS;
        const int pc = t - lr * PCOLS;
        int g = r0 + lr - 3;
        g = g < 0 ? -g : g;
        g = g < 110 - g ? g : 110 - g;
        int w = pc - 3;
        w = w < 0 ? -w : w;
        w = w < 110 - w ? w : 110 - w;
        sp[lr * RS + pc] = xin[g * W + w];
    }
    __syncthreads();

    float* __restrict__ ob0 =
        out + (size_t)plane * KK * PLANE + (size_t)r0 * W;

    const int NP = RPC * (W / 4);  // 196 float4 positions in this quarter
    for (int pos = threadIdx.x; pos < NP; pos += 64) {
        const int lrow = pos / 14;              // 0..13
        const int w0   = (pos - lrow * 14) * 4;

        // Center cols w0..w0+3 = padded cols w0+3..w0+6 of row lrow+3:
        // inside the two aligned float4s at [w0, w0+8).
        float4 center;
        {
            const float4* p =
                reinterpret_cast<const float4*>(sp + (lrow + 3) * RS + w0);
            const float4 A = p[0], B = p[1];
            center = make_float4(A.w, B.x, B.y, B.z);
        }

        float* __restrict__ ob = ob0 + lrow * W + w0;

#pragma unroll
        for (int i = 0; i < 7; ++i) {
            const float4* p =
                reinterpret_cast<const float4*>(sp + (lrow + i) * RS + w0);
            const float4 A = p[0], B = p[1], C = p[2];
            const float vv[12] = {A.x, A.y, A.z, A.w,
                                  B.x, B.y, B.z, B.w,
                                  C.x, C.y, C.z, C.w};
#pragma unroll
            for (int j = 0; j < 7; ++j) {
                float4 r;
                r.x = center.x - vv[j];
                r.y = center.y - vv[j + 1];
                r.z = center.z - vv[j + 2];
                r.w = center.w - vv[j + 3];
                // Lanes hold consecutive pos at fixed (i,j): each warp's
                // STG.128 group writes 512 contiguous bytes.
                *reinterpret_cast<float4*>(ob + (i * 7 + j) * PLANE) = r;
            }
        }
    }
}

extern "C" void kernel_launch(void* const* d_in, const int* in_sizes, int n_in,
                              void* d_out, int out_size) {
    const float* x = (const float*)d_in[0];
    float* out = (float*)d_out;
    const int planes = in_sizes[0] / PLANE;  // 512
    san_subtraction_kernel<<<planes * 4, 64>>>(x, out);
}

// round 9
// speedup vs baseline: 1.0029x; 1.0029x over previous
#include <cuda_runtime.h>
#include <cuda_bf16.h>

// SAN Subtraction: out[n,c,k,l] = x[n,c,oh,ow] - x[n,c, refl(oh+i-3), refl(ow+j-3)]
//   x: [8, 64, 56, 56] fp32, K=7, pad=3 reflect;  out: [8, 64, 49, 3136] fp32.
//
// R8: converged configuration.
//   Evidence R2-R7: kernel dur 55.4-60.2us across store mechanism, LDS
//   pattern, and CTA shape; steady-state write rate 5.7 TB/s = practical
//   HBM write ceiling. Ranking tracks wave count: one-wave 256-thr CTAs
//   (R2, 55.4) best; R4's identical loop lost 7% only to its 2-wave
//   launch_bounds(256,3) cap.
//   => R4's 58-reg conflict-free loop + launch_bounds(256,4):
//   - 1 CTA/plane, grid=512, 4 CTAs/SM -> 592 slots >= 512: ONE wave.
//   - Pre-reflected padded tile 62x62 (stride 88): zero reflect math in the
//     hot loop, all reads are aligned LDS.128, conflict-free (22 16B groups
//     per row, 22 mod 8 = 6 -> every 8-lane phase hits 8 distinct groups).
//   - Plain STG.128, lanes consecutive at fixed (i,j): 512 B contiguous
//     full-line warp stores (optimal sector utilization).
//   (Checked: no 256-bit STG on sm_103a - width encodings stop at 128.)

#define H 56
#define W 56
#define PLANE (H * W)        // 3136
#define KK 49
#define PROWS 62             // H + 2*3 halo
#define PCOLS 62             // W + 2*3 halo
#define RS 88                // smem row stride in floats
#define NPOS (H * (W / 4))   // 784 float4 positions per plane

__global__ __launch_bounds__(256, 4)
void san_subtraction_kernel(const float* __restrict__ x,
                            float* __restrict__ out) {
    __shared__ float sp[PROWS * RS];  // 21.8 KB

    const int plane = blockIdx.x;
    const float* __restrict__ xin = x + (size_t)plane * PLANE;

    // Stage pre-reflected padded tile: padded (lr,pc) -> input (lr-3, pc-3)
    // reflected.  refl(p) = min(|p|, 110-|p|), 110 = 2*(H-1).
    for (int t = threadIdx.x; t < PROWS * PCOLS; t += 256) {
        const int lr = t / PCOLS;
        const int pc = t - lr * PCOLS;
        int g = lr - 3;
        g = g < 0 ? -g : g;
        g = g < 110 - g ? g : 110 - g;
        int w = pc - 3;
        w = w < 0 ? -w : w;
        w = w < 110 - w ? w : 110 - w;
        sp[lr * RS + pc] = xin[g * W + w];
    }
    __syncthreads();

    float* __restrict__ obase = out + (size_t)plane * KK * PLANE;

    for (int pos = threadIdx.x; pos < NPOS; pos += 256) {
        const int lrow = pos / 14;              // output row 0..55
        const int w0   = (pos - lrow * 14) * 4; // output col base

        // Center cols w0..w0+3 live at padded cols w0+3..w0+6 of row lrow+3,
        // i.e. inside the two aligned float4s at [w0, w0+8).
        float4 center;
        {
            const float4* p =
                reinterpret_cast<const float4*>(sp + (lrow + 3) * RS + w0);
            const float4 A = p[0], B = p[1];
            center = make_float4(A.w, B.x, B.y, B.z);
        }

        float* __restrict__ ob = obase + lrow * W + w0;

#pragma unroll
        for (int i = 0; i < 7; ++i) {
            const float4* p =
                reinterpret_cast<const float4*>(sp + (lrow + i) * RS + w0);
            const float4 A = p[0], B = p[1], C = p[2];
            // Padded cols w0 .. w0+11 == input cols w0-3 .. w0+8.
            const float vv[12] = {A.x, A.y, A.z, A.w,
                                  B.x, B.y, B.z, B.w,
                                  C.x, C.y, C.z, C.w};
#pragma unroll
            for (int j = 0; j < 7; ++j) {
                float4 r;
                r.x = center.x - vv[j];
                r.y = center.y - vv[j + 1];
                r.z = center.z - vv[j + 2];
                r.w = center.w - vv[j + 3];
                // Lanes hold consecutive pos at fixed (i,j): each warp's
                // STG.128 group writes 512 contiguous bytes.
                *reinterpret_cast<float4*>(ob + (i * 7 + j) * PLANE) = r;
            }
        }
    }
}

extern "C" void kernel_launch(void* const* d_in, const int* in_sizes, int n_in,
                              void* d_out, int out_size) {
    const float* x = (const float*)d_in[0];
    float* out = (float*)d_out;
    const int planes = in_sizes[0] / PLANE;  // 512
    san_subtraction_kernel<<<planes, 256>>>(x, out);
}

// round 10
// speedup vs baseline: 1.0968x; 1.0936x over previous
#include <cuda_runtime.h>
#include <cuda_bf16.h>

// SAN Subtraction: out[n,c,k,l] = x[n,c,oh,ow] - x[n,c, refl(oh+i-3), refl(ow+j-3)]
//   x: [8, 64, 56, 56] fp32, K=7, stride=1, pad=3 (reflect, dilation=1)
//   out: [8, 64, 49, 3136] fp32  (H_out = W_out = 56)
//
// R9 = R2 pinned (champion: 55.4us ncu / 59.9us wall).
// Convergence evidence (R2-R8): kernel dur spans 55.4-61.5us across scalar
// vs conflict-free LDS.128, STG.128 vs TMA bulk stores, 64/128/256-thr CTAs,
// occupancy 3/4/8/16 CTAs/SM, 1-wave vs 2-wave grids. R4 vs R8 (identical
// source, occ 3 vs 4) differ by 2us in the WRONG direction -> all variants
// draw from ~57+-3us set by the sustained HBM write ceiling (~5.7 TB/s for
// this 315 MB stream). No unit above 60% in any profile; nothing else binds.
// Resubmitted byte-identical to reproduce the best-measured SASS (62 regs).
//
// Strategy: one CTA per (n,c) plane. Stage the 56x56 plane in SMEM (12.25 KB),
// so global memory sees ONLY the 315 MB write stream (DRAM-write roofline).
// Reflect indices computed arithmetically: refl(p) = min(|p-3|, 110-|p-3|).
// Each thread owns float4-wide output positions; center + all reflected
// indices hoisted out of the fully unrolled 49-way k loop.

#define H 56
#define W 56
#define PLANE (H * W)       // 3136
#define KK 49
#define NPOS (H * (W / 4))  // 784 float4 positions per plane

__global__ __launch_bounds__(256, 4)
void san_subtraction_kernel(const float* __restrict__ x,
                            float* __restrict__ out,
                            int planes) {
    __shared__ float sp[PLANE];

    const int plane = blockIdx.x;
    const float* xin = x + (size_t)plane * PLANE;

    // Stage the input plane: 784 float4 coalesced loads.
    for (int t = threadIdx.x; t < NPOS; t += blockDim.x) {
        reinterpret_cast<float4*>(sp)[t] =
            reinterpret_cast<const float4*>(xin)[t];
    }
    __syncthreads();

    float* obase = out + (size_t)plane * KK * PLANE;

    for (int pos = threadIdx.x; pos < NPOS; pos += blockDim.x) {
        const int oh = pos / 14;
        const int w0 = (pos % 14) * 4;

        // Center (aligned float4 in smem).
        const float4 c = *reinterpret_cast<const float4*>(&sp[oh * W + w0]);

        // Reflected row byte-offsets for the 7 kernel rows.
        int rr[7];
#pragma unroll
        for (int i = 0; i < 7; ++i) {
            int p = oh + i - 3;
            p = p < 0 ? -p : p;                 // abs
            p = p < 110 - p ? p : 110 - p;      // mirror top edge (110 = 2*(H-1))
            rr[i] = p * W;
        }

        // Reflected column indices for the 7 kernel cols x 4 lanes.
        int cc[7][4];
#pragma unroll
        for (int j = 0; j < 7; ++j) {
#pragma unroll
            for (int q = 0; q < 4; ++q) {
                int p = w0 + q + j - 3;
                p = p < 0 ? -p : p;
                p = p < 110 - p ? p : 110 - p;
                cc[j][q] = p;
            }
        }

        float* o = obase + pos * 4;
#pragma unroll
        for (int i = 0; i < 7; ++i) {
            const float* row = sp + rr[i];
#pragma unroll
            for (int j = 0; j < 7; ++j) {
                float4 v;
                v.x = c.x - row[cc[j][0]];
                v.y = c.y - row[cc[j][1]];
                v.z = c.z - row[cc[j][2]];
                v.w = c.w - row[cc[j][3]];
                // Warp lanes have consecutive pos at the same (i,j):
                // each STG.128 group writes 512 contiguous bytes.
                *reinterpret_cast<float4*>(o + (i * 7 + j) * PLANE) = v;
            }
        }
    }
}

extern "C" void kernel_launch(void* const* d_in, const int* in_sizes, int n_in,
                              void* d_out, int out_size) {
    const float* x = (const float*)d_in[0];
    float* out = (float*)d_out;

    const int planes = in_sizes[0] / PLANE;  // N*C = 512
    san_subtraction_kernel<<<planes, 256>>>(x, out, planes);
}